// round 2
// baseline (speedup 1.0000x reference)
#include <cuda_runtime.h>
#include <cuda_bf16.h>
#include <cstdint>
#include <cstddef>

// HierarchicalModelFusion: S=64, M=4, B=128, H=1024, nh=8, dh=128
// Stage1: x[32768,1024] -> qkv -> MHA(L=4) -> proj -> mean(M) + pos -> seq[8192,1024]
// Stage2: seq -> qkv -> MHA(L=64) -> proj -> transpose -> out[64,128,1,1024]

#define SROW 36
#define TILE_FLOATS (128 * SROW)
#define GEMM_SMEM (6 * TILE_FLOATS * 4)

__device__ float g_buf0[100663296];  // qkv1 [32768,3072]; reused y1, qkv2
__device__ float g_buf1[33554432];   // attn1 out [32768,1024]; reused attn2 out
__device__ float g_buf2[8388608];    // seq [8192,1024]

__device__ __forceinline__ unsigned f2tf(float x) {
    unsigned r;
    asm("cvt.rna.tf32.f32 %0, %1;" : "=r"(r) : "f"(x));
    return r;
}
__device__ __forceinline__ void mma8(float c[4], const unsigned a[4], const unsigned b[2]) {
    asm volatile(
        "mma.sync.aligned.m16n8k8.row.col.f32.tf32.tf32.f32 "
        "{%0,%1,%2,%3}, {%4,%5,%6,%7}, {%8,%9}, {%0,%1,%2,%3};"
        : "+f"(c[0]), "+f"(c[1]), "+f"(c[2]), "+f"(c[3])
        : "r"(a[0]), "r"(a[1]), "r"(a[2]), "r"(a[3]), "r"(b[0]), "r"(b[1]));
}
__device__ __forceinline__ void cp16(float* s, const float* g) {
    unsigned sa = (unsigned)__cvta_generic_to_shared(s);
    asm volatile("cp.async.cg.shared.global [%0], [%1], 16;" :: "r"(sa), "l"(g));
}
__device__ __forceinline__ void cp_commit() { asm volatile("cp.async.commit_group;"); }
__device__ __forceinline__ void cp_wait1()  { asm volatile("cp.async.wait_group 1;"); }

// C[M,N] = A[M,K] @ W[N,K]^T + bias ; 3xTF32 split
// a_mode=1: A row r reads hidden row s*512+m*128+b for r=(s*128+b)*4+m
// c_mode=1: C row r=b*64+s written to row s*128+b
__global__ __launch_bounds__(256) void gemm3x(
    const float* __restrict__ A, const float* __restrict__ W,
    const float* __restrict__ bias, float* __restrict__ C,
    int M, int N, int K, int a_mode, int c_mode)
{
    extern __shared__ float smem[];
    float* As = smem;
    float* Bs = smem + 3 * TILE_FLOATS;

    const int tid = threadIdx.x;
    const int lane = tid & 31;
    const int warp = tid >> 5;
    const int wm = warp >> 2;
    const int wn = warp & 3;
    const int bm = blockIdx.y;
    const int bn = blockIdx.x;
    const int NCHUNK = K >> 5;

    const float* aptr[4];
    const float* wptr[4];
    int soff[4];
#pragma unroll
    for (int i = 0; i < 4; i++) {
        int flat = tid + i * 256;
        int row = flat >> 3;
        int k4 = flat & 7;
        soff[i] = row * SROW + k4 * 4;
        int ar = bm * 128 + row;
        if (a_mode) {
            int s = ar >> 9, b = (ar >> 2) & 127, m = ar & 3;
            ar = s * 512 + m * 128 + b;
        }
        aptr[i] = A + (size_t)ar * K + k4 * 4;
        wptr[i] = W + (size_t)(bn * 128 + row) * K + k4 * 4;
    }

#pragma unroll
    for (int c = 0; c < 2; c++) {
#pragma unroll
        for (int i = 0; i < 4; i++) {
            cp16(As + c * TILE_FLOATS + soff[i], aptr[i] + c * 32);
            cp16(Bs + c * TILE_FLOATS + soff[i], wptr[i] + c * 32);
        }
        cp_commit();
    }

    float acc[4][4][4];
#pragma unroll
    for (int a = 0; a < 4; a++)
#pragma unroll
        for (int b = 0; b < 4; b++)
#pragma unroll
            for (int c = 0; c < 4; c++) acc[a][b][c] = 0.f;

    int stage = 0;
    for (int ch = 0; ch < NCHUNK; ch++) {
        cp_wait1();
        __syncthreads();

        if (ch + 2 < NCHUNK) {
            int st2 = stage + 2; if (st2 >= 3) st2 -= 3;
#pragma unroll
            for (int i = 0; i < 4; i++) {
                cp16(As + st2 * TILE_FLOATS + soff[i], aptr[i] + (ch + 2) * 32);
                cp16(Bs + st2 * TILE_FLOATS + soff[i], wptr[i] + (ch + 2) * 32);
            }
        }
        cp_commit();

        const float* as = As + stage * TILE_FLOATS;
        const float* bs = Bs + stage * TILE_FLOATS;

#pragma unroll
        for (int kk = 0; kk < 4; kk++) {
            const int krow = kk * 8 + (lane & 3);
            const int g = lane >> 2;
            unsigned ah[4][4], al[4][4], bh[4][2], bl[4][2];
#pragma unroll
            for (int mt = 0; mt < 4; mt++) {
                int r0 = (wm * 64 + mt * 16 + g) * SROW + krow;
                float x0 = as[r0];
                float x1 = as[r0 + 8 * SROW];
                float x2 = as[r0 + 4];
                float x3 = as[r0 + 8 * SROW + 4];
                ah[mt][0] = f2tf(x0); al[mt][0] = f2tf(x0 - __uint_as_float(ah[mt][0]));
                ah[mt][1] = f2tf(x1); al[mt][1] = f2tf(x1 - __uint_as_float(ah[mt][1]));
                ah[mt][2] = f2tf(x2); al[mt][2] = f2tf(x2 - __uint_as_float(ah[mt][2]));
                ah[mt][3] = f2tf(x3); al[mt][3] = f2tf(x3 - __uint_as_float(ah[mt][3]));
            }
#pragma unroll
            for (int nt = 0; nt < 4; nt++) {
                int n0 = (wn * 32 + nt * 8 + g) * SROW + krow;
                float y0 = bs[n0];
                float y1 = bs[n0 + 4];
                bh[nt][0] = f2tf(y0); bl[nt][0] = f2tf(y0 - __uint_as_float(bh[nt][0]));
                bh[nt][1] = f2tf(y1); bl[nt][1] = f2tf(y1 - __uint_as_float(bh[nt][1]));
            }
#pragma unroll
            for (int mt = 0; mt < 4; mt++)
#pragma unroll
                for (int nt = 0; nt < 4; nt++) {
                    mma8(acc[mt][nt], al[mt], bh[nt]);
                    mma8(acc[mt][nt], ah[mt], bl[nt]);
                    mma8(acc[mt][nt], ah[mt], bh[nt]);
                }
        }
        stage++; if (stage >= 3) stage = 0;
    }

    const int g = lane >> 2;
    const int c2 = (lane & 3) * 2;
#pragma unroll
    for (int mt = 0; mt < 4; mt++) {
        int row0 = bm * 128 + wm * 64 + mt * 16 + g;
#pragma unroll
        for (int nt = 0; nt < 4; nt++) {
            int col = bn * 128 + wn * 32 + nt * 8 + c2;
            float b0 = __ldg(bias + col);
            float b1 = __ldg(bias + col + 1);
            int ra = row0, rb = row0 + 8;
            if (c_mode) {
                ra = (ra & 63) * 128 + (ra >> 6);
                rb = (rb & 63) * 128 + (rb >> 6);
            }
            float2 v0 = make_float2(acc[mt][nt][0] + b0, acc[mt][nt][1] + b1);
            float2 v1 = make_float2(acc[mt][nt][2] + b0, acc[mt][nt][3] + b1);
            *reinterpret_cast<float2*>(C + (size_t)ra * N + col) = v0;
            *reinterpret_cast<float2*>(C + (size_t)rb * N + col) = v1;
        }
    }
}

// Stage-1 attention, L=4. One block per (sb, head); 128 threads (= dh).
__global__ __launch_bounds__(128) void attn_small(
    const float* __restrict__ qkv, float* __restrict__ out)
{
    const int bid = blockIdx.x;
    const int sb = bid >> 3;
    const int h = bid & 7;
    const int t = threadIdx.x;

    const float* base = qkv + (size_t)sb * 4 * 3072 + h * 128 + t;
    float q[4], k[4], v[4];
#pragma unroll
    for (int m = 0; m < 4; m++) {
        q[m] = base[(size_t)m * 3072];
        k[m] = base[(size_t)m * 3072 + 1024];
        v[m] = base[(size_t)m * 3072 + 2048];
    }

    float p[16];
#pragma unroll
    for (int a = 0; a < 4; a++)
#pragma unroll
        for (int b = 0; b < 4; b++) p[a * 4 + b] = q[a] * k[b];

    __shared__ float red[4][16];
    __shared__ float ssc[16];
    const int lane = t & 31, w = t >> 5;
#pragma unroll
    for (int i = 0; i < 16; i++) {
        float x = p[i];
        x += __shfl_xor_sync(0xffffffffu, x, 16);
        x += __shfl_xor_sync(0xffffffffu, x, 8);
        x += __shfl_xor_sync(0xffffffffu, x, 4);
        x += __shfl_xor_sync(0xffffffffu, x, 2);
        x += __shfl_xor_sync(0xffffffffu, x, 1);
        if (lane == 0) red[w][i] = x;
    }
    __syncthreads();
    if (t < 16) ssc[t] = red[0][t] + red[1][t] + red[2][t] + red[3][t];
    __syncthreads();

    const float scale = 0.08838834764831845f;  // 1/sqrt(128)
    float att[16];
#pragma unroll
    for (int a = 0; a < 4; a++) {
        float s0 = ssc[a * 4 + 0], s1 = ssc[a * 4 + 1];
        float s2 = ssc[a * 4 + 2], s3 = ssc[a * 4 + 3];
        float mx = fmaxf(fmaxf(s0, s1), fmaxf(s2, s3));
        float e0 = __expf((s0 - mx) * scale);
        float e1 = __expf((s1 - mx) * scale);
        float e2 = __expf((s2 - mx) * scale);
        float e3 = __expf((s3 - mx) * scale);
        float inv = 1.f / (e0 + e1 + e2 + e3);
        att[a * 4 + 0] = e0 * inv; att[a * 4 + 1] = e1 * inv;
        att[a * 4 + 2] = e2 * inv; att[a * 4 + 3] = e3 * inv;
    }

    float* ob = out + (size_t)sb * 4 * 1024 + h * 128 + t;
#pragma unroll
    for (int a = 0; a < 4; a++) {
        float o = att[a * 4 + 0] * v[0] + att[a * 4 + 1] * v[1]
                + att[a * 4 + 2] * v[2] + att[a * 4 + 3] * v[3];
        ob[(size_t)a * 1024] = o;
    }
}

// mean over M=4 + positional enc; y rows [(s*128+b)*4+m] -> seq row [b*64+s]
__global__ __launch_bounds__(256) void reduce_pos(
    const float* __restrict__ y, const float* __restrict__ pos, float* __restrict__ seq)
{
    int e = blockIdx.x * 256 + threadIdx.x;
    int hcol = e & 1023;
    int bs = e >> 10;
    int b = bs >> 6, s = bs & 63;
    const float* yr = y + ((size_t)(s * 128 + b) * 4) * 1024 + hcol;
    float v = 0.25f * (yr[0] + yr[1024] + yr[2048] + yr[3072]);
    seq[e] = v + pos[s * 1024 + hcol];
}

// Stage-2 attention, L=64, dh=128. One block per (b, head); 256 threads.
#define AQ_STRIDE 68
#define AV_STRIDE 132
#define SC_STRIDE 65
#define ATTN2_SMEM ((128 * AQ_STRIDE * 2 + 64 * AV_STRIDE + 64 * SC_STRIDE) * 4)

__global__ __launch_bounds__(256) void attn_big(
    const float* __restrict__ qkv, float* __restrict__ out)
{
    extern __shared__ float sm[];
    float* qs = sm;                        // [128][AQ_STRIDE]  q^T [d][i]
    float* ks = qs + 128 * AQ_STRIDE;      // [128][AQ_STRIDE]  k^T [d][j]
    float* vs = ks + 128 * AQ_STRIDE;      // [64][AV_STRIDE]   v   [j][d]
    float* sc = vs + 64 * AV_STRIDE;       // [64][SC_STRIDE]

    const int bid = blockIdx.x;
    const int b = bid >> 3;
    const int h = bid & 7;
    const int t = threadIdx.x;

    const float* base = qkv + (size_t)b * 64 * 3072 + h * 128;

#pragma unroll
    for (int i = 0; i < 8; i++) {
        int flat = t + i * 256;
        int j = flat >> 5, d4 = flat & 31;
        const float* rp = base + (size_t)j * 3072 + d4 * 4;
        float4 qv = *reinterpret_cast<const float4*>(rp);
        float4 kv = *reinterpret_cast<const float4*>(rp + 1024);
        float4 vv = *reinterpret_cast<const float4*>(rp + 2048);
        int d0 = d4 * 4;
        qs[(d0 + 0) * AQ_STRIDE + j] = qv.x;
        qs[(d0 + 1) * AQ_STRIDE + j] = qv.y;
        qs[(d0 + 2) * AQ_STRIDE + j] = qv.z;
        qs[(d0 + 3) * AQ_STRIDE + j] = qv.w;
        ks[(d0 + 0) * AQ_STRIDE + j] = kv.x;
        ks[(d0 + 1) * AQ_STRIDE + j] = kv.y;
        ks[(d0 + 2) * AQ_STRIDE + j] = kv.z;
        ks[(d0 + 3) * AQ_STRIDE + j] = kv.w;
        *reinterpret_cast<float4*>(vs + j * AV_STRIDE + d0) = vv;
    }
    __syncthreads();

    // S = Q @ K^T : each thread a 4x4 tile of the 64x64 score matrix
    {
        const int gi = t >> 4;
        const int gj = t & 15;
        float s4[4][4];
#pragma unroll
        for (int a = 0; a < 4; a++)
#pragma unroll
            for (int c = 0; c < 4; c++) s4[a][c] = 0.f;
#pragma unroll 4
        for (int d = 0; d < 128; d++) {
            float4 qv = *reinterpret_cast<const float4*>(qs + d * AQ_STRIDE + gi * 4);
            float4 kv = *reinterpret_cast<const float4*>(ks + d * AQ_STRIDE + gj * 4);
            float qa[4] = {qv.x, qv.y, qv.z, qv.w};
            float ka[4] = {kv.x, kv.y, kv.z, kv.w};
#pragma unroll
            for (int a = 0; a < 4; a++)
#pragma unroll
                for (int c = 0; c < 4; c++) s4[a][c] += qa[a] * ka[c];
        }
        int i0 = gi * 4, j0 = gj * 4;
#pragma unroll
        for (int a = 0; a < 4; a++) {
            float* r = sc + (i0 + a) * SC_STRIDE + j0;
            r[0] = s4[a][0]; r[1] = s4[a][1]; r[2] = s4[a][2]; r[3] = s4[a][3];
        }
    }
    __syncthreads();

    if (t < 64) {
        float* row = sc + t * SC_STRIDE;
        float mx = -1e30f;
#pragma unroll 8
        for (int j = 0; j < 64; j++) mx = fmaxf(mx, row[j]);
        const float scale = 0.08838834764831845f;
        float sum = 0.f;
#pragma unroll 8
        for (int j = 0; j < 64; j++) {
            float e = __expf((row[j] - mx) * scale);
            row[j] = e;
            sum += e;
        }
        float inv = 1.f / sum;
#pragma unroll 8
        for (int j = 0; j < 64; j++) row[j] *= inv;
    }
    __syncthreads();

    // O = P @ V : each thread 4 rows x 8 cols (4 in each 64-col half)
    {
        const int gi = t >> 4;
        const int gd = t & 15;
        const int i0 = gi * 4;
        float o[4][8];
#pragma unroll
        for (int r = 0; r < 4; r++)
#pragma unroll
            for (int c = 0; c < 8; c++) o[r][c] = 0.f;
#pragma unroll 4
        for (int j = 0; j < 64; j++) {
            const float* vr = vs + j * AV_STRIDE + gd * 4;
            float p0 = sc[(i0 + 0) * SC_STRIDE + j];
            float p1 = sc[(i0 + 1) * SC_STRIDE + j];
            float p2 = sc[(i0 + 2) * SC_STRIDE + j];
            float p3 = sc[(i0 + 3) * SC_STRIDE + j];
#pragma unroll
            for (int c = 0; c < 4; c++) {
                float va = vr[c];
                float vb = vr[64 + c];
                o[0][c] += p0 * va; o[0][c + 4] += p0 * vb;
                o[1][c] += p1 * va; o[1][c + 4] += p1 * vb;
                o[2][c] += p2 * va; o[2][c + 4] += p2 * vb;
                o[3][c] += p3 * va; o[3][c + 4] += p3 * vb;
            }
        }
        float* ob = out + (size_t)(b * 64 + i0) * 1024 + h * 128 + gd * 4;
#pragma unroll
        for (int r = 0; r < 4; r++) {
            *reinterpret_cast<float4*>(ob + (size_t)r * 1024) =
                make_float4(o[r][0], o[r][1], o[r][2], o[r][3]);
            *reinterpret_cast<float4*>(ob + (size_t)r * 1024 + 64) =
                make_float4(o[r][4], o[r][5], o[r][6], o[r][7]);
        }
    }
}

extern "C" void kernel_launch(void* const* d_in, const int* in_sizes, int n_in,
                              void* d_out, int out_size) {
    const float* hidden   = (const float*)d_in[0];
    const float* mf_in_w  = (const float*)d_in[1];
    const float* mf_in_b  = (const float*)d_in[2];
    const float* mf_out_w = (const float*)d_in[3];
    const float* mf_out_b = (const float*)d_in[4];
    const float* sf_in_w  = (const float*)d_in[5];
    const float* sf_in_b  = (const float*)d_in[6];
    const float* sf_out_w = (const float*)d_in[7];
    const float* sf_out_b = (const float*)d_in[8];
    const float* pos_enc  = (const float*)d_in[9];
    float* out = (float*)d_out;

    float *buf0, *buf1, *buf2;
    cudaGetSymbolAddress((void**)&buf0, g_buf0);
    cudaGetSymbolAddress((void**)&buf1, g_buf1);
    cudaGetSymbolAddress((void**)&buf2, g_buf2);

    cudaFuncSetAttribute(gemm3x, cudaFuncAttributeMaxDynamicSharedMemorySize, GEMM_SMEM);
    cudaFuncSetAttribute(attn_big, cudaFuncAttributeMaxDynamicSharedMemorySize, ATTN2_SMEM);

    // 1) qkv1 = x @ mf_in_w^T + b   (x gathered from hidden)
    gemm3x<<<dim3(24, 256), 256, GEMM_SMEM>>>(hidden, mf_in_w, mf_in_b, buf0,
                                              32768, 3072, 1024, 1, 0);
    // 2) MHA over M=4
    attn_small<<<65536, 128>>>(buf0, buf1);
    // 3) y1 = attn1 @ mf_out_w^T + b
    gemm3x<<<dim3(8, 256), 256, GEMM_SMEM>>>(buf1, mf_out_w, mf_out_b, buf0,
                                             32768, 1024, 1024, 0, 0);
    // 4) mean over M + pos enc -> seq [b*64+s]
    reduce_pos<<<32768, 256>>>(buf0, pos_enc, buf2);
    // 5) qkv2 = seq @ sf_in_w^T + b
    gemm3x<<<dim3(24, 64), 256, GEMM_SMEM>>>(buf2, sf_in_w, sf_in_b, buf0,
                                             8192, 3072, 1024, 0, 0);
    // 6) MHA over S=64
    attn_big<<<1024, 256, ATTN2_SMEM>>>(buf0, buf1);
    // 7) out = (attn2 @ sf_out_w^T + b) with [b,s]->[s,b] transpose
    gemm3x<<<dim3(8, 64), 256, GEMM_SMEM>>>(buf1, sf_out_w, sf_out_b, out,
                                            8192, 1024, 1024, 0, 1);
}

// round 5
// speedup vs baseline: 1.9486x; 1.9486x over previous
#include <cuda_runtime.h>
#include <cuda_bf16.h>
#include <cstdint>
#include <cstddef>

// HierarchicalModelFusion: S=64, M=4, B=128, H=1024, nh=8, dh=128
// 3-term bf16-split GEMMs (Ah*Wh + Ah*Wl + Al*Wh), splits precomputed outside
// the hot loop. GEMM inner loop = LDS.32 + mma.m16n8k16.bf16 only.

#define ASTRIDE 40                                   // bf16 elems per smem row (80B)
#define S_AH 0
#define S_AL (128 * ASTRIDE)
#define S_BH (2 * 128 * ASTRIDE)
#define S_BL (2 * 128 * ASTRIDE + 256 * ASTRIDE)
#define STAGE_ELEMS (2 * 128 * ASTRIDE + 2 * 256 * ASTRIDE)   // 30720 bf16
#define GEMM_SMEM (3 * STAGE_ELEMS * 2)              // 184320 B

#define XLO 33554432            // lo-offset inside g_x (elems)
#define SLO 8388608             // lo-offset inside g_s
#define WLO 8388608             // lo-offset inside g_w
// weight hi-region offsets inside g_w
#define W_MFIN  0
#define W_MFOUT 3145728
#define W_SFIN  4194304
#define W_SFOUT 7340032

__device__ float g_bufA[100663296];          // qkv1 [32768,3072] f32; reused y1, qkv2
__device__ __nv_bfloat16 g_x[67108864];      // hi[0..33M) lo[33M..67M): x / attn1 / attn2
__device__ __nv_bfloat16 g_s[16777216];      // seq hi/lo
__device__ __nv_bfloat16 g_w[16777216];      // weights hi/lo

// ---------------------------------------------------------------------------
__device__ __forceinline__ void split1(float x, unsigned short& h, unsigned short& l) {
    __nv_bfloat16 hb = __float2bfloat16_rn(x);
    __nv_bfloat16 lb = __float2bfloat16_rn(x - __bfloat162float(hb));
    h = __bfloat16_as_ushort(hb);
    l = __bfloat16_as_ushort(lb);
}
__device__ __forceinline__ unsigned pack2(unsigned short a, unsigned short b) {
    return (unsigned)a | ((unsigned)b << 16);
}

__device__ __forceinline__ void mma16(float c[4], const unsigned a[4], const unsigned b[2]) {
    asm volatile(
        "mma.sync.aligned.m16n8k16.row.col.f32.bf16.bf16.f32 "
        "{%0,%1,%2,%3}, {%4,%5,%6,%7}, {%8,%9}, {%0,%1,%2,%3};"
        : "+f"(c[0]), "+f"(c[1]), "+f"(c[2]), "+f"(c[3])
        : "r"(a[0]), "r"(a[1]), "r"(a[2]), "r"(a[3]), "r"(b[0]), "r"(b[1]));
}
__device__ __forceinline__ void cp16(void* s, const void* g) {
    unsigned sa = (unsigned)__cvta_generic_to_shared(s);
    asm volatile("cp.async.cg.shared.global [%0], [%1], 16;" :: "r"(sa), "l"(g));
}
__device__ __forceinline__ void cp_commit() { asm volatile("cp.async.commit_group;"); }
__device__ __forceinline__ void cp_wait1()  { asm volatile("cp.async.wait_group 1;"); }

// ---------------------------------------------------------------------------
// elementwise fp32 -> bf16 hi/lo split
__global__ __launch_bounds__(256) void split_plain(
    const float* __restrict__ src, __nv_bfloat16* __restrict__ hi, __nv_bfloat16* __restrict__ lo)
{
    size_t i = (size_t)blockIdx.x * 256 + threadIdx.x;
    float4 v = *reinterpret_cast<const float4*>(src + i * 4);
    unsigned short h0,h1,h2,h3,l0,l1,l2,l3;
    split1(v.x,h0,l0); split1(v.y,h1,l1); split1(v.z,h2,l2); split1(v.w,h3,l3);
    *reinterpret_cast<uint2*>(hi + i * 4) = make_uint2(pack2(h0,h1), pack2(h2,h3));
    *reinterpret_cast<uint2*>(lo + i * 4) = make_uint2(pack2(l0,l1), pack2(l2,l3));
}

// x gather (hidden [S,M,B,1,H] -> rows r=(s*128+b)*4+m) + split
__global__ __launch_bounds__(256) void split_x(
    const float* __restrict__ hidden, __nv_bfloat16* __restrict__ hi, __nv_bfloat16* __restrict__ lo)
{
    size_t i = (size_t)blockIdx.x * 256 + threadIdx.x;   // one float4 each, 8.4M total
    int r = (int)(i >> 8);
    int c4 = ((int)i & 255) * 4;
    int s = r >> 9, b = (r >> 2) & 127, m = r & 3;
    const float4 v = *reinterpret_cast<const float4*>(
        hidden + (size_t)(s * 512 + m * 128 + b) * 1024 + c4);
    unsigned short h0,h1,h2,h3,l0,l1,l2,l3;
    split1(v.x,h0,l0); split1(v.y,h1,l1); split1(v.z,h2,l2); split1(v.w,h3,l3);
    *reinterpret_cast<uint2*>(hi + i * 4) = make_uint2(pack2(h0,h1), pack2(h2,h3));
    *reinterpret_cast<uint2*>(lo + i * 4) = make_uint2(pack2(l0,l1), pack2(l2,l3));
}

// ---------------------------------------------------------------------------
// C[M,N] = (Ah+Al)(Wh+Wl)^T + bias (3-term). Block tile 128x256x32, 8 warps
// in 2x4 grid, warp tile 64x64. A/W are bf16 hi arrays; lo at +aLo/+wLo elems.
// c_mode=1: row r=b*64+s stored to row s*128+b (final transpose).
__global__ __launch_bounds__(256, 1) void gemm_bf3(
    const __nv_bfloat16* __restrict__ A, int aLo,
    const __nv_bfloat16* __restrict__ W, int wLo,
    const float* __restrict__ bias, float* __restrict__ C,
    int N, int K, int c_mode)
{
    extern __shared__ __nv_bfloat16 sm[];
    const int tid = threadIdx.x, lane = tid & 31, warp = tid >> 5;
    const int wm = warp >> 2, wn = warp & 3;
    const int bm = blockIdx.y, bn = blockIdx.x;
    const int NCH = K >> 5;

    int aoff[4], adst[4], boff[8], bdst[8];
#pragma unroll
    for (int i = 0; i < 4; i++) {
        int flat = tid + i * 256, row = flat >> 3, seg = flat & 7, ks = seg & 3;
        aoff[i] = ((seg < 4) ? 0 : aLo) + (bm * 128 + row) * K + ks * 8;
        adst[i] = ((seg < 4) ? S_AH : S_AL) + row * ASTRIDE + ks * 8;
    }
#pragma unroll
    for (int i = 0; i < 8; i++) {
        int flat = tid + i * 256, row = flat >> 3, seg = flat & 7, ks = seg & 3;
        boff[i] = ((seg < 4) ? 0 : wLo) + (bn * 256 + row) * K + ks * 8;
        bdst[i] = ((seg < 4) ? S_BH : S_BL) + row * ASTRIDE + ks * 8;
    }

#pragma unroll
    for (int c = 0; c < 2; c++) {
#pragma unroll
        for (int i = 0; i < 4; i++) cp16(sm + c * STAGE_ELEMS + adst[i], A + aoff[i] + c * 32);
#pragma unroll
        for (int i = 0; i < 8; i++) cp16(sm + c * STAGE_ELEMS + bdst[i], W + boff[i] + c * 32);
        cp_commit();
    }

    float acc[4][8][4];
#pragma unroll
    for (int a = 0; a < 4; a++)
#pragma unroll
        for (int b = 0; b < 8; b++)
#pragma unroll
            for (int c = 0; c < 4; c++) acc[a][b][c] = 0.f;

    const int g = lane >> 2, q2 = 2 * (lane & 3);

    int stage = 0;
    for (int ch = 0; ch < NCH; ch++) {
        cp_wait1();
        __syncthreads();

        if (ch + 2 < NCH) {
            int st2 = stage + 2; if (st2 >= 3) st2 -= 3;
#pragma unroll
            for (int i = 0; i < 4; i++)
                cp16(sm + st2 * STAGE_ELEMS + adst[i], A + aoff[i] + (ch + 2) * 32);
#pragma unroll
            for (int i = 0; i < 8; i++)
                cp16(sm + st2 * STAGE_ELEMS + bdst[i], W + boff[i] + (ch + 2) * 32);
        }
        cp_commit();

        const __nv_bfloat16* st = sm + stage * STAGE_ELEMS;

#pragma unroll
        for (int kt = 0; kt < 2; kt++) {
            const int kb = kt * 16 + q2;

            unsigned ah[4][4];
#pragma unroll
            for (int mb = 0; mb < 4; mb++) {
                const __nv_bfloat16* p = st + S_AH + (wm * 64 + mb * 16 + g) * ASTRIDE + kb;
                ah[mb][0] = *reinterpret_cast<const unsigned*>(p);
                ah[mb][1] = *reinterpret_cast<const unsigned*>(p + 8 * ASTRIDE);
                ah[mb][2] = *reinterpret_cast<const unsigned*>(p + 8);
                ah[mb][3] = *reinterpret_cast<const unsigned*>(p + 8 * ASTRIDE + 8);
            }
            unsigned bh[8][2];
#pragma unroll
            for (int nb = 0; nb < 8; nb++) {
                const __nv_bfloat16* p = st + S_BH + (wn * 64 + nb * 8 + g) * ASTRIDE + kb;
                bh[nb][0] = *reinterpret_cast<const unsigned*>(p);
                bh[nb][1] = *reinterpret_cast<const unsigned*>(p + 8);
            }
#pragma unroll
            for (int mb = 0; mb < 4; mb++)
#pragma unroll
                for (int nb = 0; nb < 8; nb++) mma16(acc[mb][nb], ah[mb], bh[nb]);

            unsigned bl[8][2];
#pragma unroll
            for (int nb = 0; nb < 8; nb++) {
                const __nv_bfloat16* p = st + S_BL + (wn * 64 + nb * 8 + g) * ASTRIDE + kb;
                bl[nb][0] = *reinterpret_cast<const unsigned*>(p);
                bl[nb][1] = *reinterpret_cast<const unsigned*>(p + 8);
            }
#pragma unroll
            for (int mb = 0; mb < 4; mb++)
#pragma unroll
                for (int nb = 0; nb < 8; nb++) mma16(acc[mb][nb], ah[mb], bl[nb]);

            unsigned al[4][4];
#pragma unroll
            for (int mb = 0; mb < 4; mb++) {
                const __nv_bfloat16* p = st + S_AL + (wm * 64 + mb * 16 + g) * ASTRIDE + kb;
                al[mb][0] = *reinterpret_cast<const unsigned*>(p);
                al[mb][1] = *reinterpret_cast<const unsigned*>(p + 8 * ASTRIDE);
                al[mb][2] = *reinterpret_cast<const unsigned*>(p + 8);
                al[mb][3] = *reinterpret_cast<const unsigned*>(p + 8 * ASTRIDE + 8);
            }
#pragma unroll
            for (int mb = 0; mb < 4; mb++)
#pragma unroll
                for (int nb = 0; nb < 8; nb++) mma16(acc[mb][nb], al[mb], bh[nb]);
        }
        stage++; if (stage >= 3) stage = 0;
    }

    // epilogue
#pragma unroll
    for (int mb = 0; mb < 4; mb++) {
        int row0 = bm * 128 + wm * 64 + mb * 16 + g;
#pragma unroll
        for (int nb = 0; nb < 8; nb++) {
            int col = bn * 256 + wn * 64 + nb * 8 + q2;
            float b0 = __ldg(bias + col);
            float b1 = __ldg(bias + col + 1);
            int ra = row0, rb = row0 + 8;
            if (c_mode) {
                ra = (ra & 63) * 128 + (ra >> 6);
                rb = (rb & 63) * 128 + (rb >> 6);
            }
            *reinterpret_cast<float2*>(C + (size_t)ra * N + col) =
                make_float2(acc[mb][nb][0] + b0, acc[mb][nb][1] + b1);
            *reinterpret_cast<float2*>(C + (size_t)rb * N + col) =
                make_float2(acc[mb][nb][2] + b0, acc[mb][nb][3] + b1);
        }
    }
}

// ---------------------------------------------------------------------------
// Stage-1 attention, L=4; writes bf16 hi/lo split output.
__global__ __launch_bounds__(128) void attn_small(
    const float* __restrict__ qkv, __nv_bfloat16* __restrict__ ohi, __nv_bfloat16* __restrict__ olo)
{
    const int bid = blockIdx.x;
    const int sb = bid >> 3;
    const int h = bid & 7;
    const int t = threadIdx.x;

    const float* base = qkv + (size_t)sb * 4 * 3072 + h * 128 + t;
    float q[4], k[4], v[4];
#pragma unroll
    for (int m = 0; m < 4; m++) {
        q[m] = base[(size_t)m * 3072];
        k[m] = base[(size_t)m * 3072 + 1024];
        v[m] = base[(size_t)m * 3072 + 2048];
    }

    float p[16];
#pragma unroll
    for (int a = 0; a < 4; a++)
#pragma unroll
        for (int b = 0; b < 4; b++) p[a * 4 + b] = q[a] * k[b];

    __shared__ float red[4][16];
    __shared__ float ssc[16];
    const int lane = t & 31, w = t >> 5;
#pragma unroll
    for (int i = 0; i < 16; i++) {
        float x = p[i];
        x += __shfl_xor_sync(0xffffffffu, x, 16);
        x += __shfl_xor_sync(0xffffffffu, x, 8);
        x += __shfl_xor_sync(0xffffffffu, x, 4);
        x += __shfl_xor_sync(0xffffffffu, x, 2);
        x += __shfl_xor_sync(0xffffffffu, x, 1);
        if (lane == 0) red[w][i] = x;
    }
    __syncthreads();
    if (t < 16) ssc[t] = red[0][t] + red[1][t] + red[2][t] + red[3][t];
    __syncthreads();

    const float scale = 0.08838834764831845f;
    float att[16];
#pragma unroll
    for (int a = 0; a < 4; a++) {
        float s0 = ssc[a*4+0], s1 = ssc[a*4+1], s2 = ssc[a*4+2], s3 = ssc[a*4+3];
        float mx = fmaxf(fmaxf(s0, s1), fmaxf(s2, s3));
        float e0 = __expf((s0 - mx) * scale);
        float e1 = __expf((s1 - mx) * scale);
        float e2 = __expf((s2 - mx) * scale);
        float e3 = __expf((s3 - mx) * scale);
        float inv = 1.f / (e0 + e1 + e2 + e3);
        att[a*4+0] = e0*inv; att[a*4+1] = e1*inv; att[a*4+2] = e2*inv; att[a*4+3] = e3*inv;
    }

#pragma unroll
    for (int a = 0; a < 4; a++) {
        float o = att[a*4+0]*v[0] + att[a*4+1]*v[1] + att[a*4+2]*v[2] + att[a*4+3]*v[3];
        size_t idx = (size_t)sb * 4 * 1024 + (size_t)a * 1024 + h * 128 + t;
        unsigned short hh, ll;
        split1(o, hh, ll);
        ohi[idx] = __ushort_as_bfloat16(hh);
        olo[idx] = __ushort_as_bfloat16(ll);
    }
}

// mean over M=4 + pos enc; y rows [(s*128+b)*4+m] -> seq row [b*64+s]; bf16 split out
__global__ __launch_bounds__(256) void reduce_pos(
    const float* __restrict__ y, const float* __restrict__ pos,
    __nv_bfloat16* __restrict__ shi, __nv_bfloat16* __restrict__ slo)
{
    int e = blockIdx.x * 256 + threadIdx.x;
    int hcol = e & 1023;
    int bs = e >> 10;
    int b = bs >> 6, s = bs & 63;
    const float* yr = y + ((size_t)(s * 128 + b) * 4) * 1024 + hcol;
    float v = 0.25f * (yr[0] + yr[1024] + yr[2048] + yr[3072]) + pos[s * 1024 + hcol];
    unsigned short hh, ll;
    split1(v, hh, ll);
    shi[e] = __ushort_as_bfloat16(hh);
    slo[e] = __ushort_as_bfloat16(ll);
}

// ---------------------------------------------------------------------------
// Stage-2 attention, L=64, dh=128; bf16 hi/lo split output.
#define AQ_STRIDE 68
#define AV_STRIDE 132
#define SC_STRIDE 65
#define ATTN2_SMEM ((128 * AQ_STRIDE * 2 + 64 * AV_STRIDE + 64 * SC_STRIDE) * 4)

__global__ __launch_bounds__(256) void attn_big(
    const float* __restrict__ qkv, __nv_bfloat16* __restrict__ ohi, __nv_bfloat16* __restrict__ olo)
{
    extern __shared__ float smf[];
    float* qs = smf;
    float* ks = qs + 128 * AQ_STRIDE;
    float* vs = ks + 128 * AQ_STRIDE;
    float* sc = vs + 64 * AV_STRIDE;

    const int bid = blockIdx.x;
    const int b = bid >> 3;
    const int h = bid & 7;
    const int t = threadIdx.x;

    const float* base = qkv + (size_t)b * 64 * 3072 + h * 128;

#pragma unroll
    for (int i = 0; i < 8; i++) {
        int flat = t + i * 256;
        int j = flat >> 5, d4 = flat & 31;
        const float* rp = base + (size_t)j * 3072 + d4 * 4;
        float4 qv = *reinterpret_cast<const float4*>(rp);
        float4 kv = *reinterpret_cast<const float4*>(rp + 1024);
        float4 vv = *reinterpret_cast<const float4*>(rp + 2048);
        int d0 = d4 * 4;
        qs[(d0+0)*AQ_STRIDE + j] = qv.x; qs[(d0+1)*AQ_STRIDE + j] = qv.y;
        qs[(d0+2)*AQ_STRIDE + j] = qv.z; qs[(d0+3)*AQ_STRIDE + j] = qv.w;
        ks[(d0+0)*AQ_STRIDE + j] = kv.x; ks[(d0+1)*AQ_STRIDE + j] = kv.y;
        ks[(d0+2)*AQ_STRIDE + j] = kv.z; ks[(d0+3)*AQ_STRIDE + j] = kv.w;
        *reinterpret_cast<float4*>(vs + j * AV_STRIDE + d0) = vv;
    }
    __syncthreads();

    {
        const int gi = t >> 4, gj = t & 15;
        float s4[4][4];
#pragma unroll
        for (int a = 0; a < 4; a++)
#pragma unroll
            for (int c = 0; c < 4; c++) s4[a][c] = 0.f;
#pragma unroll 4
        for (int d = 0; d < 128; d++) {
            float4 qv = *reinterpret_cast<const float4*>(qs + d * AQ_STRIDE + gi * 4);
            float4 kv = *reinterpret_cast<const float4*>(ks + d * AQ_STRIDE + gj * 4);
            float qa[4] = {qv.x, qv.y, qv.z, qv.w};
            float ka[4] = {kv.x, kv.y, kv.z, kv.w};
#pragma unroll
            for (int a = 0; a < 4; a++)
#pragma unroll
                for (int c = 0; c < 4; c++) s4[a][c] += qa[a] * ka[c];
        }
        int i0 = gi * 4, j0 = gj * 4;
#pragma unroll
        for (int a = 0; a < 4; a++) {
            float* r = sc + (i0 + a) * SC_STRIDE + j0;
            r[0]=s4[a][0]; r[1]=s4[a][1]; r[2]=s4[a][2]; r[3]=s4[a][3];
        }
    }
    __syncthreads();

    if (t < 64) {
        float* row = sc + t * SC_STRIDE;
        float mx = -1e30f;
#pragma unroll 8
        for (int j = 0; j < 64; j++) mx = fmaxf(mx, row[j]);
        const float scale = 0.08838834764831845f;
        float sum = 0.f;
#pragma unroll 8
        for (int j = 0; j < 64; j++) {
            float e = __expf((row[j] - mx) * scale);
            row[j] = e;
            sum += e;
        }
        float inv = 1.f / sum;
#pragma unroll 8
        for (int j = 0; j < 64; j++) row[j] *= inv;
    }
    __syncthreads();

    {
        const int gi = t >> 4, gd = t & 15;
        const int i0 = gi * 4;
        float o[4][8];
#pragma unroll
        for (int r = 0; r < 4; r++)
#pragma unroll
            for (int c = 0; c < 8; c++) o[r][c] = 0.f;
#pragma unroll 4
        for (int j = 0; j < 64; j++) {
            const float* vr = vs + j * AV_STRIDE + gd * 4;
            float p0 = sc[(i0+0)*SC_STRIDE + j];
            float p1 = sc[(i0+1)*SC_STRIDE + j];
            float p2 = sc[(i0+2)*SC_STRIDE + j];
            float p3 = sc[(i0+3)*SC_STRIDE + j];
#pragma unroll
            for (int c = 0; c < 4; c++) {
                float va = vr[c], vb = vr[64 + c];
                o[0][c] += p0*va; o[0][c+4] += p0*vb;
                o[1][c] += p1*va; o[1][c+4] += p1*vb;
                o[2][c] += p2*va; o[2][c+4] += p2*vb;
                o[3][c] += p3*va; o[3][c+4] += p3*vb;
            }
        }
#pragma unroll
        for (int r = 0; r < 4; r++) {
            size_t idx = (size_t)(b * 64 + i0 + r) * 1024 + h * 128 + gd * 4;
#pragma unroll
            for (int half = 0; half < 2; half++) {
                unsigned short h0,h1,h2,h3,l0,l1,l2,l3;
                split1(o[r][half*4+0], h0, l0);
                split1(o[r][half*4+1], h1, l1);
                split1(o[r][half*4+2], h2, l2);
                split1(o[r][half*4+3], h3, l3);
                size_t ix = idx + half * 64;
                *reinterpret_cast<uint2*>(ohi + ix) = make_uint2(pack2(h0,h1), pack2(h2,h3));
                *reinterpret_cast<uint2*>(olo + ix) = make_uint2(pack2(l0,l1), pack2(l2,l3));
            }
        }
    }
}

// ---------------------------------------------------------------------------
extern "C" void kernel_launch(void* const* d_in, const int* in_sizes, int n_in,
                              void* d_out, int out_size) {
    const float* hidden   = (const float*)d_in[0];
    const float* mf_in_w  = (const float*)d_in[1];
    const float* mf_in_b  = (const float*)d_in[2];
    const float* mf_out_w = (const float*)d_in[3];
    const float* mf_out_b = (const float*)d_in[4];
    const float* sf_in_w  = (const float*)d_in[5];
    const float* sf_in_b  = (const float*)d_in[6];
    const float* sf_out_w = (const float*)d_in[7];
    const float* sf_out_b = (const float*)d_in[8];
    const float* pos_enc  = (const float*)d_in[9];
    float* out = (float*)d_out;

    float *bufA;
    __nv_bfloat16 *bx, *bs, *bw;
    cudaGetSymbolAddress((void**)&bufA, g_bufA);
    cudaGetSymbolAddress((void**)&bx, g_x);
    cudaGetSymbolAddress((void**)&bs, g_s);
    cudaGetSymbolAddress((void**)&bw, g_w);

    cudaFuncSetAttribute(gemm_bf3, cudaFuncAttributeMaxDynamicSharedMemorySize, GEMM_SMEM);
    cudaFuncSetAttribute(attn_big, cudaFuncAttributeMaxDynamicSharedMemorySize, ATTN2_SMEM);

    // weight splits (hi at W_*, lo at +WLO)
    split_plain<<<3072, 256>>>(mf_in_w,  bw + W_MFIN,  bw + WLO + W_MFIN);
    split_plain<<<1024, 256>>>(mf_out_w, bw + W_MFOUT, bw + WLO + W_MFOUT);
    split_plain<<<3072, 256>>>(sf_in_w,  bw + W_SFIN,  bw + WLO + W_SFIN);
    split_plain<<<1024, 256>>>(sf_out_w, bw + W_SFOUT, bw + WLO + W_SFOUT);

    // x gather + split
    split_x<<<32768, 256>>>(hidden, bx, bx + XLO);

    // 1) qkv1 = x @ mf_in_w^T + b
    gemm_bf3<<<dim3(12, 256), 256, GEMM_SMEM>>>(bx, XLO, bw + W_MFIN, WLO,
                                                mf_in_b, bufA, 3072, 1024, 0);
    // 2) MHA over M=4 (writes hi/lo into bx, reusing x space)
    attn_small<<<65536, 128>>>(bufA, bx, bx + XLO);
    // 3) y1 = attn1 @ mf_out_w^T + b  (bufA dead after attn_small -> reuse)
    gemm_bf3<<<dim3(4, 256), 256, GEMM_SMEM>>>(bx, XLO, bw + W_MFOUT, WLO,
                                               mf_out_b, bufA, 1024, 1024, 0);
    // 4) mean + pos -> seq (split)
    reduce_pos<<<32768, 256>>>(bufA, pos_enc, bs, bs + SLO);
    // 5) qkv2 = seq @ sf_in_w^T + b  (bufA dead after reduce_pos -> reuse)
    gemm_bf3<<<dim3(12, 64), 256, GEMM_SMEM>>>(bs, SLO, bw + W_SFIN, WLO,
                                               sf_in_b, bufA, 3072, 1024, 0);
    // 6) MHA over S=64 (writes hi/lo into bx)
    attn_big<<<1024, 256, ATTN2_SMEM>>>(bufA, bx, bx + XLO);
    // 7) out = (attn2 @ sf_out_w^T + b), [b,s]->[s,b] transpose
    gemm_bf3<<<dim3(4, 64), 256, GEMM_SMEM>>>(bx, XLO, bw + W_SFOUT, WLO,
                                              sf_out_b, out, 1024, 1024, 1);
}

// round 13
// speedup vs baseline: 2.0376x; 1.0457x over previous
#include <cuda_runtime.h>
#include <cuda_bf16.h>
#include <cstdint>
#include <cstddef>

// HierarchicalModelFusion: S=64, M=4, B=128, H=1024, nh=8, dh=128
// 3-term bf16-split GEMMs (Ah*Wh + Ah*Wl + Al*Wh) on mma.sync.m16n8k16,
// ldmatrix fragment loads, 512 threads (16 warps), 3-stage cp.async pipeline.
// NOTE: tcgen05 is NOT available in this harness (ptxas target sm_103, not sm_103a).

#define ASTRIDE 40                                   // bf16 elems per smem row (80B)
#define S_AH 0
#define S_AL (128 * ASTRIDE)
#define S_BH (2 * 128 * ASTRIDE)
#define S_BL (2 * 128 * ASTRIDE + 256 * ASTRIDE)
#define STAGE_ELEMS (2 * 128 * ASTRIDE + 2 * 256 * ASTRIDE)   // 30720 bf16
#define GEMM_SMEM (3 * STAGE_ELEMS * 2)              // 184320 B

#define XLO 33554432            // lo-offset inside g_x (elems)
#define SLO 8388608             // lo-offset inside g_s
#define WLO 8388608             // lo-offset inside g_w
#define W_MFIN  0
#define W_MFOUT 3145728
#define W_SFIN  4194304
#define W_SFOUT 7340032

__device__ float g_bufA[100663296];          // qkv f32; reused y1, qkv2
__device__ __nv_bfloat16 g_x[67108864];      // hi[0..33M) lo[33M..67M)
__device__ __nv_bfloat16 g_s[16777216];      // seq hi/lo
__device__ __nv_bfloat16 g_w[16777216];      // weights hi/lo

// ---------------------------------------------------------------------------
__device__ __forceinline__ void split1(float x, unsigned short& h, unsigned short& l) {
    __nv_bfloat16 hb = __float2bfloat16_rn(x);
    __nv_bfloat16 lb = __float2bfloat16_rn(x - __bfloat162float(hb));
    h = __bfloat16_as_ushort(hb);
    l = __bfloat16_as_ushort(lb);
}
__device__ __forceinline__ unsigned pack2(unsigned short a, unsigned short b) {
    return (unsigned)a | ((unsigned)b << 16);
}
__device__ __forceinline__ void mma16(float c[4], const unsigned a[4], const unsigned b[2]) {
    asm volatile(
        "mma.sync.aligned.m16n8k16.row.col.f32.bf16.bf16.f32 "
        "{%0,%1,%2,%3}, {%4,%5,%6,%7}, {%8,%9}, {%0,%1,%2,%3};"
        : "+f"(c[0]), "+f"(c[1]), "+f"(c[2]), "+f"(c[3])
        : "r"(a[0]), "r"(a[1]), "r"(a[2]), "r"(a[3]), "r"(b[0]), "r"(b[1]));
}
__device__ __forceinline__ void ldsm4(unsigned r[4], uint32_t addr) {
    asm volatile("ldmatrix.sync.aligned.m8n8.x4.shared.b16 {%0,%1,%2,%3}, [%4];"
        : "=r"(r[0]), "=r"(r[1]), "=r"(r[2]), "=r"(r[3]) : "r"(addr));
}
__device__ __forceinline__ void cp16(void* s, const void* g) {
    unsigned sa = (unsigned)__cvta_generic_to_shared(s);
    asm volatile("cp.async.cg.shared.global [%0], [%1], 16;" :: "r"(sa), "l"(g));
}
__device__ __forceinline__ void cp_commit() { asm volatile("cp.async.commit_group;"); }
__device__ __forceinline__ void cp_wait1()  { asm volatile("cp.async.wait_group 1;"); }

// ---------------------------------------------------------------------------
// C[M,N] = (Ah+Al)(Wh+Wl)^T + bias (3-term). Block tile 128x256x32, 16 warps
// in 4x4 grid, warp tile 32x64. ldmatrix fragment loads.
// c_mode=1: row r=b*64+s stored to row s*128+b (final transpose).
__global__ __launch_bounds__(512, 1) void gemm_bf3(
    const __nv_bfloat16* __restrict__ A, int aLo,
    const __nv_bfloat16* __restrict__ W, int wLo,
    const float* __restrict__ bias, float* __restrict__ C,
    int N, int K, int c_mode)
{
    extern __shared__ __nv_bfloat16 sm[];
    const int tid = threadIdx.x, lane = tid & 31, warp = tid >> 5;
    const int wm = warp >> 2, wn = warp & 3;
    const int bm = blockIdx.y, bn = blockIdx.x;
    const int NCH = K >> 5;

    // cp.async descriptors: A 1024 16B-segs (2 iters), W 2048 segs (4 iters)
    int aoff[2], adst[2], boff[4], bdst[4];
#pragma unroll
    for (int i = 0; i < 2; i++) {
        int flat = tid + i * 512, row = flat >> 3, seg = flat & 7, ks = seg & 3;
        aoff[i] = ((seg < 4) ? 0 : aLo) + (bm * 128 + row) * K + ks * 8;
        adst[i] = ((seg < 4) ? S_AH : S_AL) + row * ASTRIDE + ks * 8;
    }
#pragma unroll
    for (int i = 0; i < 4; i++) {
        int flat = tid + i * 512, row = flat >> 3, seg = flat & 7, ks = seg & 3;
        boff[i] = ((seg < 4) ? 0 : wLo) + (bn * 256 + row) * K + ks * 8;
        bdst[i] = ((seg < 4) ? S_BH : S_BL) + row * ASTRIDE + ks * 8;
    }

#pragma unroll
    for (int c = 0; c < 2; c++) {
#pragma unroll
        for (int i = 0; i < 2; i++) cp16(sm + c * STAGE_ELEMS + adst[i], A + aoff[i] + c * 32);
#pragma unroll
        for (int i = 0; i < 4; i++) cp16(sm + c * STAGE_ELEMS + bdst[i], W + boff[i] + c * 32);
        cp_commit();
    }

    float acc[2][8][4];
#pragma unroll
    for (int a = 0; a < 2; a++)
#pragma unroll
        for (int b = 0; b < 8; b++)
#pragma unroll
            for (int c = 0; c < 4; c++) acc[a][b][c] = 0.f;

    // ldmatrix per-lane element offsets (in bf16 elems, within a stage)
    // A (m16k16, x4): lanes 0-7 m0(row+0..7,k+0), 8-15 m1(row+8..,k+0),
    //                 16-23 m2(row+0..,k+8), 24-31 m3(row+8..,k+8)
    const int aRow = wm * 32 + (lane & 8) + (lane & 7);
    const int aoffH_e = S_AH + aRow * ASTRIDE + ((lane & 16) >> 1);
    const int aoffL_e = S_AL + aRow * ASTRIDE + ((lane & 16) >> 1);
    // B (two n8 tiles per x4): lanes 0-7 m0(n+0..7,k+0), 8-15 m1(n+0..7,k+8),
    //                          16-23 m2(n+8..15,k+0), 24-31 m3(n+8..15,k+8)
    const int bRow = wn * 64 + ((lane & 16) >> 1) + (lane & 7);
    const int boffH_e = S_BH + bRow * ASTRIDE + (lane & 8);
    const int boffL_e = S_BL + bRow * ASTRIDE + (lane & 8);

    const uint32_t smb = (uint32_t)__cvta_generic_to_shared(sm);

    int stage = 0;
    for (int ch = 0; ch < NCH; ch++) {
        cp_wait1();
        __syncthreads();

        if (ch + 2 < NCH) {
            int st2 = stage + 2; if (st2 >= 3) st2 -= 3;
#pragma unroll
            for (int i = 0; i < 2; i++)
                cp16(sm + st2 * STAGE_ELEMS + adst[i], A + aoff[i] + (ch + 2) * 32);
#pragma unroll
            for (int i = 0; i < 4; i++)
                cp16(sm + st2 * STAGE_ELEMS + bdst[i], W + boff[i] + (ch + 2) * 32);
        }
        cp_commit();

        const uint32_t sbase = smb + stage * (STAGE_ELEMS * 2);

#pragma unroll
        for (int kt = 0; kt < 2; kt++) {
            const uint32_t kbyte = kt * 32;   // kt*16 elems * 2B

            unsigned ah[2][4];
#pragma unroll
            for (int mb = 0; mb < 2; mb++)
                ldsm4(ah[mb], sbase + (uint32_t)(aoffH_e + mb * 16 * ASTRIDE) * 2 + kbyte);

            unsigned bh[8][2];
#pragma unroll
            for (int p = 0; p < 4; p++) {
                unsigned r[4];
                ldsm4(r, sbase + (uint32_t)(boffH_e + p * 16 * ASTRIDE) * 2 + kbyte);
                bh[2*p][0] = r[0]; bh[2*p][1] = r[1];
                bh[2*p+1][0] = r[2]; bh[2*p+1][1] = r[3];
            }
#pragma unroll
            for (int mb = 0; mb < 2; mb++)
#pragma unroll
                for (int nb = 0; nb < 8; nb++) mma16(acc[mb][nb], ah[mb], bh[nb]);

            unsigned bl[8][2];
#pragma unroll
            for (int p = 0; p < 4; p++) {
                unsigned r[4];
                ldsm4(r, sbase + (uint32_t)(boffL_e + p * 16 * ASTRIDE) * 2 + kbyte);
                bl[2*p][0] = r[0]; bl[2*p][1] = r[1];
                bl[2*p+1][0] = r[2]; bl[2*p+1][1] = r[3];
            }
#pragma unroll
            for (int mb = 0; mb < 2; mb++)
#pragma unroll
                for (int nb = 0; nb < 8; nb++) mma16(acc[mb][nb], ah[mb], bl[nb]);

            unsigned al[2][4];
#pragma unroll
            for (int mb = 0; mb < 2; mb++)
                ldsm4(al[mb], sbase + (uint32_t)(aoffL_e + mb * 16 * ASTRIDE) * 2 + kbyte);
#pragma unroll
            for (int mb = 0; mb < 2; mb++)
#pragma unroll
                for (int nb = 0; nb < 8; nb++) mma16(acc[mb][nb], al[mb], bh[nb]);
        }
        stage++; if (stage >= 3) stage = 0;
    }

    // epilogue
    const int g = lane >> 2, q2 = 2 * (lane & 3);
#pragma unroll
    for (int mb = 0; mb < 2; mb++) {
        int row0 = bm * 128 + wm * 32 + mb * 16 + g;
#pragma unroll
        for (int nb = 0; nb < 8; nb++) {
            int col = bn * 256 + wn * 64 + nb * 8 + q2;
            float b0 = __ldg(bias + col);
            float b1 = __ldg(bias + col + 1);
            int ra = row0, rb = row0 + 8;
            if (c_mode) {
                ra = (ra & 63) * 128 + (ra >> 6);
                rb = (rb & 63) * 128 + (rb >> 6);
            }
            *reinterpret_cast<float2*>(C + (size_t)ra * N + col) =
                make_float2(acc[mb][nb][0] + b0, acc[mb][nb][1] + b1);
            *reinterpret_cast<float2*>(C + (size_t)rb * N + col) =
                make_float2(acc[mb][nb][2] + b0, acc[mb][nb][3] + b1);
        }
    }
}

// ---------------------------------------------------------------------------
__global__ __launch_bounds__(256) void split_plain(
    const float* __restrict__ src, __nv_bfloat16* __restrict__ hi, __nv_bfloat16* __restrict__ lo)
{
    size_t i = (size_t)blockIdx.x * 256 + threadIdx.x;
    float4 v = *reinterpret_cast<const float4*>(src + i * 4);
    unsigned short h0,h1,h2,h3,l0,l1,l2,l3;
    split1(v.x,h0,l0); split1(v.y,h1,l1); split1(v.z,h2,l2); split1(v.w,h3,l3);
    *reinterpret_cast<uint2*>(hi + i * 4) = make_uint2(pack2(h0,h1), pack2(h2,h3));
    *reinterpret_cast<uint2*>(lo + i * 4) = make_uint2(pack2(l0,l1), pack2(l2,l3));
}

__global__ __launch_bounds__(256) void split_x(
    const float* __restrict__ hidden, __nv_bfloat16* __restrict__ hi, __nv_bfloat16* __restrict__ lo)
{
    size_t i = (size_t)blockIdx.x * 256 + threadIdx.x;
    int r = (int)(i >> 8);
    int c4 = ((int)i & 255) * 4;
    int s = r >> 9, b = (r >> 2) & 127, m = r & 3;
    const float4 v = *reinterpret_cast<const float4*>(
        hidden + (size_t)(s * 512 + m * 128 + b) * 1024 + c4);
    unsigned short h0,h1,h2,h3,l0,l1,l2,l3;
    split1(v.x,h0,l0); split1(v.y,h1,l1); split1(v.z,h2,l2); split1(v.w,h3,l3);
    *reinterpret_cast<uint2*>(hi + i * 4) = make_uint2(pack2(h0,h1), pack2(h2,h3));
    *reinterpret_cast<uint2*>(lo + i * 4) = make_uint2(pack2(l0,l1), pack2(l2,l3));
}

// ---------------------------------------------------------------------------
__global__ __launch_bounds__(128) void attn_small(
    const float* __restrict__ qkv, __nv_bfloat16* __restrict__ ohi, __nv_bfloat16* __restrict__ olo)
{
    const int bid = blockIdx.x;
    const int sb = bid >> 3;
    const int h = bid & 7;
    const int t = threadIdx.x;

    const float* base = qkv + (size_t)sb * 4 * 3072 + h * 128 + t;
    float q[4], k[4], v[4];
#pragma unroll
    for (int m = 0; m < 4; m++) {
        q[m] = base[(size_t)m * 3072];
        k[m] = base[(size_t)m * 3072 + 1024];
        v[m] = base[(size_t)m * 3072 + 2048];
    }

    float p[16];
#pragma unroll
    for (int a = 0; a < 4; a++)
#pragma unroll
        for (int b = 0; b < 4; b++) p[a * 4 + b] = q[a] * k[b];

    __shared__ float red[4][16];
    __shared__ float ssc[16];
    const int lane = t & 31, w = t >> 5;
#pragma unroll
    for (int i = 0; i < 16; i++) {
        float x = p[i];
        x += __shfl_xor_sync(0xffffffffu, x, 16);
        x += __shfl_xor_sync(0xffffffffu, x, 8);
        x += __shfl_xor_sync(0xffffffffu, x, 4);
        x += __shfl_xor_sync(0xffffffffu, x, 2);
        x += __shfl_xor_sync(0xffffffffu, x, 1);
        if (lane == 0) red[w][i] = x;
    }
    __syncthreads();
    if (t < 16) ssc[t] = red[0][t] + red[1][t] + red[2][t] + red[3][t];
    __syncthreads();

    const float scale = 0.08838834764831845f;
    float att[16];
#pragma unroll
    for (int a = 0; a < 4; a++) {
        float s0 = ssc[a*4+0], s1 = ssc[a*4+1], s2 = ssc[a*4+2], s3 = ssc[a*4+3];
        float mx = fmaxf(fmaxf(s0, s1), fmaxf(s2, s3));
        float e0 = __expf((s0 - mx) * scale);
        float e1 = __expf((s1 - mx) * scale);
        float e2 = __expf((s2 - mx) * scale);
        float e3 = __expf((s3 - mx) * scale);
        float inv = 1.f / (e0 + e1 + e2 + e3);
        att[a*4+0] = e0*inv; att[a*4+1] = e1*inv; att[a*4+2] = e2*inv; att[a*4+3] = e3*inv;
    }

#pragma unroll
    for (int a = 0; a < 4; a++) {
        float o = att[a*4+0]*v[0] + att[a*4+1]*v[1] + att[a*4+2]*v[2] + att[a*4+3]*v[3];
        size_t idx = (size_t)sb * 4 * 1024 + (size_t)a * 1024 + h * 128 + t;
        unsigned short hh, ll;
        split1(o, hh, ll);
        ohi[idx] = __ushort_as_bfloat16(hh);
        olo[idx] = __ushort_as_bfloat16(ll);
    }
}

__global__ __launch_bounds__(256) void reduce_pos(
    const float* __restrict__ y, const float* __restrict__ pos,
    __nv_bfloat16* __restrict__ shi, __nv_bfloat16* __restrict__ slo)
{
    int e = blockIdx.x * 256 + threadIdx.x;
    int hcol = e & 1023;
    int bs = e >> 10;
    int b = bs >> 6, s = bs & 63;
    const float* yr = y + ((size_t)(s * 128 + b) * 4) * 1024 + hcol;
    float v = 0.25f * (yr[0] + yr[1024] + yr[2048] + yr[3072]) + pos[s * 1024 + hcol];
    unsigned short hh, ll;
    split1(v, hh, ll);
    shi[e] = __ushort_as_bfloat16(hh);
    slo[e] = __ushort_as_bfloat16(ll);
}

// ---------------------------------------------------------------------------
#define AQ_STRIDE 68
#define AV_STRIDE 132
#define SC_STRIDE 65
#define ATTN2_SMEM ((128 * AQ_STRIDE * 2 + 64 * AV_STRIDE + 64 * SC_STRIDE) * 4)

__global__ __launch_bounds__(256) void attn_big(
    const float* __restrict__ qkv, __nv_bfloat16* __restrict__ ohi, __nv_bfloat16* __restrict__ olo)
{
    extern __shared__ float smf[];
    float* qs = smf;
    float* ks = qs + 128 * AQ_STRIDE;
    float* vs = ks + 128 * AQ_STRIDE;
    float* sc = vs + 64 * AV_STRIDE;

    const int bid = blockIdx.x;
    const int b = bid >> 3;
    const int h = bid & 7;
    const int t = threadIdx.x;

    const float* base = qkv + (size_t)b * 64 * 3072 + h * 128;

#pragma unroll
    for (int i = 0; i < 8; i++) {
        int flat = t + i * 256;
        int j = flat >> 5, d4 = flat & 31;
        const float* rp = base + (size_t)j * 3072 + d4 * 4;
        float4 qv = *reinterpret_cast<const float4*>(rp);
        float4 kv = *reinterpret_cast<const float4*>(rp + 1024);
        float4 vv = *reinterpret_cast<const float4*>(rp + 2048);
        int d0 = d4 * 4;
        qs[(d0+0)*AQ_STRIDE + j] = qv.x; qs[(d0+1)*AQ_STRIDE + j] = qv.y;
        qs[(d0+2)*AQ_STRIDE + j] = qv.z; qs[(d0+3)*AQ_STRIDE + j] = qv.w;
        ks[(d0+0)*AQ_STRIDE + j] = kv.x; ks[(d0+1)*AQ_STRIDE + j] = kv.y;
        ks[(d0+2)*AQ_STRIDE + j] = kv.z; ks[(d0+3)*AQ_STRIDE + j] = kv.w;
        *reinterpret_cast<float4*>(vs + j * AV_STRIDE + d0) = vv;
    }
    __syncthreads();

    {
        const int gi = t >> 4, gj = t & 15;
        float s4[4][4];
#pragma unroll
        for (int a = 0; a < 4; a++)
#pragma unroll
            for (int c = 0; c < 4; c++) s4[a][c] = 0.f;
#pragma unroll 4
        for (int d = 0; d < 128; d++) {
            float4 qv = *reinterpret_cast<const float4*>(qs + d * AQ_STRIDE + gi * 4);
            float4 kv = *reinterpret_cast<const float4*>(ks + d * AQ_STRIDE + gj * 4);
            float qa[4] = {qv.x, qv.y, qv.z, qv.w};
            float ka[4] = {kv.x, kv.y, kv.z, kv.w};
#pragma unroll
            for (int a = 0; a < 4; a++)
#pragma unroll
                for (int c = 0; c < 4; c++) s4[a][c] += qa[a] * ka[c];
        }
        int i0 = gi * 4, j0 = gj * 4;
#pragma unroll
        for (int a = 0; a < 4; a++) {
            float* r = sc + (i0 + a) * SC_STRIDE + j0;
            r[0]=s4[a][0]; r[1]=s4[a][1]; r[2]=s4[a][2]; r[3]=s4[a][3];
        }
    }
    __syncthreads();

    if (t < 64) {
        float* row = sc + t * SC_STRIDE;
        float mx = -1e30f;
#pragma unroll 8
        for (int j = 0; j < 64; j++) mx = fmaxf(mx, row[j]);
        const float scale = 0.08838834764831845f;
        float sum = 0.f;
#pragma unroll 8
        for (int j = 0; j < 64; j++) {
            float e = __expf((row[j] - mx) * scale);
            row[j] = e;
            sum += e;
        }
        float inv = 1.f / sum;
#pragma unroll 8
        for (int j = 0; j < 64; j++) row[j] *= inv;
    }
    __syncthreads();

    {
        const int gi = t >> 4, gd = t & 15;
        const int i0 = gi * 4;
        float o[4][8];
#pragma unroll
        for (int r = 0; r < 4; r++)
#pragma unroll
            for (int c = 0; c < 8; c++) o[r][c] = 0.f;
#pragma unroll 4
        for (int j = 0; j < 64; j++) {
            const float* vr = vs + j * AV_STRIDE + gd * 4;
            float p0 = sc[(i0+0)*SC_STRIDE + j];
            float p1 = sc[(i0+1)*SC_STRIDE + j];
            float p2 = sc[(i0+2)*SC_STRIDE + j];
            float p3 = sc[(i0+3)*SC_STRIDE + j];
#pragma unroll
            for (int c = 0; c < 4; c++) {
                float va = vr[c], vb = vr[64 + c];
                o[0][c] += p0*va; o[0][c+4] += p0*vb;
                o[1][c] += p1*va; o[1][c+4] += p1*vb;
                o[2][c] += p2*va; o[2][c+4] += p2*vb;
                o[3][c] += p3*va; o[3][c+4] += p3*vb;
            }
        }
#pragma unroll
        for (int r = 0; r < 4; r++) {
            size_t idx = (size_t)(b * 64 + i0 + r) * 1024 + h * 128 + gd * 4;
#pragma unroll
            for (int half = 0; half < 2; half++) {
                unsigned short h0,h1,h2,h3,l0,l1,l2,l3;
                split1(o[r][half*4+0], h0, l0);
                split1(o[r][half*4+1], h1, l1);
                split1(o[r][half*4+2], h2, l2);
                split1(o[r][half*4+3], h3, l3);
                size_t ix = idx + half * 64;
                *reinterpret_cast<uint2*>(ohi + ix) = make_uint2(pack2(h0,h1), pack2(h2,h3));
                *reinterpret_cast<uint2*>(olo + ix) = make_uint2(pack2(l0,l1), pack2(l2,l3));
            }
        }
    }
}

// ---------------------------------------------------------------------------
extern "C" void kernel_launch(void* const* d_in, const int* in_sizes, int n_in,
                              void* d_out, int out_size) {
    const float* hidden   = (const float*)d_in[0];
    const float* mf_in_w  = (const float*)d_in[1];
    const float* mf_in_b  = (const float*)d_in[2];
    const float* mf_out_w = (const float*)d_in[3];
    const float* mf_out_b = (const float*)d_in[4];
    const float* sf_in_w  = (const float*)d_in[5];
    const float* sf_in_b  = (const float*)d_in[6];
    const float* sf_out_w = (const float*)d_in[7];
    const float* sf_out_b = (const float*)d_in[8];
    const float* pos_enc  = (const float*)d_in[9];
    float* out = (float*)d_out;

    float *bufA;
    __nv_bfloat16 *bx, *bs, *bw;
    cudaGetSymbolAddress((void**)&bufA, g_bufA);
    cudaGetSymbolAddress((void**)&bx, g_x);
    cudaGetSymbolAddress((void**)&bs, g_s);
    cudaGetSymbolAddress((void**)&bw, g_w);

    cudaFuncSetAttribute(gemm_bf3, cudaFuncAttributeMaxDynamicSharedMemorySize, GEMM_SMEM);
    cudaFuncSetAttribute(attn_big, cudaFuncAttributeMaxDynamicSharedMemorySize, ATTN2_SMEM);

    // weight splits (hi at W_*, lo at +WLO)
    split_plain<<<3072, 256>>>(mf_in_w,  bw + W_MFIN,  bw + WLO + W_MFIN);
    split_plain<<<1024, 256>>>(mf_out_w, bw + W_MFOUT, bw + WLO + W_MFOUT);
    split_plain<<<3072, 256>>>(sf_in_w,  bw + W_SFIN,  bw + WLO + W_SFIN);
    split_plain<<<1024, 256>>>(sf_out_w, bw + W_SFOUT, bw + WLO + W_SFOUT);

    // x gather + split
    split_x<<<32768, 256>>>(hidden, bx, bx + XLO);

    // 1) qkv1 = x @ mf_in_w^T + b
    gemm_bf3<<<dim3(12, 256), 512, GEMM_SMEM>>>(bx, XLO, bw + W_MFIN, WLO,
                                                mf_in_b, bufA, 3072, 1024, 0);
    // 2) MHA over M=4
    attn_small<<<65536, 128>>>(bufA, bx, bx + XLO);
    // 3) y1 = attn1 @ mf_out_w^T + b (bufA dead -> reuse)
    gemm_bf3<<<dim3(4, 256), 512, GEMM_SMEM>>>(bx, XLO, bw + W_MFOUT, WLO,
                                               mf_out_b, bufA, 1024, 1024, 0);
    // 4) mean + pos -> seq (split)
    reduce_pos<<<32768, 256>>>(bufA, pos_enc, bs, bs + SLO);
    // 5) qkv2 = seq @ sf_in_w^T + b
    gemm_bf3<<<dim3(12, 64), 512, GEMM_SMEM>>>(bs, SLO, bw + W_SFIN, WLO,
                                               sf_in_b, bufA, 3072, 1024, 0);
    // 6) MHA over S=64
    attn_big<<<1024, 256, ATTN2_SMEM>>>(bufA, bx, bx + XLO);
    // 7) out = (attn2 @ sf_out_w^T + b), [b,s]->[s,b] transpose
    gemm_bf3<<<dim3(4, 64), 512, GEMM_SMEM>>>(bx, XLO, bw + W_SFOUT, WLO,
                                              sf_out_b, out, 1024, 1024, 1);
}

// round 16
// speedup vs baseline: 2.3471x; 1.1519x over previous
#include <cuda_runtime.h>
#include <cuda_bf16.h>
#include <cstdint>
#include <cstddef>

// HierarchicalModelFusion: S=64, M=4, B=128, H=1024, nh=8, dh=128
// 3-term bf16-split GEMMs on mma.sync.m16n8k16 + ldmatrix, 16 warps.
// Mean-over-M folded BEFORE the stage-1 projection (linearity) -> GEMM3 is 4x smaller.
// NOTE: tcgen05 unavailable in this harness (ptxas target sm_103, not sm_103a).

#define ASTRIDE 40                                   // bf16 elems per smem row (80B)
#define S_AH 0
#define S_AL (128 * ASTRIDE)
#define S_BH (2 * 128 * ASTRIDE)
#define S_BL (2 * 128 * ASTRIDE + 256 * ASTRIDE)
#define STAGE_ELEMS (2 * 128 * ASTRIDE + 2 * 256 * ASTRIDE)   // 30720 bf16
#define GEMM_SMEM (3 * STAGE_ELEMS * 2)              // 184320 B

#define XLO 33554432            // lo-offset inside g_x (elems)
#define SLO 8388608             // lo-offset inside g_s
#define WLO 8388608             // lo-offset inside g_w
#define W_MFIN  0
#define W_MFOUT 3145728
#define W_SFIN  4194304
#define W_SFOUT 7340032

__device__ float g_bufA[100663296];          // qkv f32; reused y1, qkv2
__device__ __nv_bfloat16 g_x[67108864];      // hi[0..33M) lo[33M..67M)
__device__ __nv_bfloat16 g_s[16777216];      // seq hi/lo
__device__ __nv_bfloat16 g_w[16777216];      // weights hi/lo

// ---------------------------------------------------------------------------
__device__ __forceinline__ void split1(float x, unsigned short& h, unsigned short& l) {
    __nv_bfloat16 hb = __float2bfloat16_rn(x);
    __nv_bfloat16 lb = __float2bfloat16_rn(x - __bfloat162float(hb));
    h = __bfloat16_as_ushort(hb);
    l = __bfloat16_as_ushort(lb);
}
__device__ __forceinline__ unsigned pack2(unsigned short a, unsigned short b) {
    return (unsigned)a | ((unsigned)b << 16);
}
__device__ __forceinline__ void mma16(float c[4], const unsigned a[4], const unsigned b[2]) {
    asm volatile(
        "mma.sync.aligned.m16n8k16.row.col.f32.bf16.bf16.f32 "
        "{%0,%1,%2,%3}, {%4,%5,%6,%7}, {%8,%9}, {%0,%1,%2,%3};"
        : "+f"(c[0]), "+f"(c[1]), "+f"(c[2]), "+f"(c[3])
        : "r"(a[0]), "r"(a[1]), "r"(a[2]), "r"(a[3]), "r"(b[0]), "r"(b[1]));
}
__device__ __forceinline__ void ldsm4(unsigned r[4], uint32_t addr) {
    asm volatile("ldmatrix.sync.aligned.m8n8.x4.shared.b16 {%0,%1,%2,%3}, [%4];"
        : "=r"(r[0]), "=r"(r[1]), "=r"(r[2]), "=r"(r[3]) : "r"(addr));
}
__device__ __forceinline__ void cp16(void* s, const void* g) {
    unsigned sa = (unsigned)__cvta_generic_to_shared(s);
    asm volatile("cp.async.cg.shared.global [%0], [%1], 16;" :: "r"(sa), "l"(g));
}
__device__ __forceinline__ void cp_commit() { asm volatile("cp.async.commit_group;"); }
__device__ __forceinline__ void cp_wait1()  { asm volatile("cp.async.wait_group 1;"); }

// ---------------------------------------------------------------------------
// C[M,N] = (Ah+Al)(Wh+Wl)^T + bias (3-term). Block tile 128x256x32, 16 warps
// in 4x4 grid, warp tile 32x64. ldmatrix fragment loads.
// c_mode=1: row r=b*64+s stored to row s*128+b (final transpose).
__global__ __launch_bounds__(512, 1) void gemm_bf3(
    const __nv_bfloat16* __restrict__ A, int aLo,
    const __nv_bfloat16* __restrict__ W, int wLo,
    const float* __restrict__ bias, float* __restrict__ C,
    int N, int K, int c_mode)
{
    extern __shared__ __nv_bfloat16 sm[];
    const int tid = threadIdx.x, lane = tid & 31, warp = tid >> 5;
    const int wm = warp >> 2, wn = warp & 3;
    const int bm = blockIdx.y, bn = blockIdx.x;
    const int NCH = K >> 5;

    int aoff[2], adst[2], boff[4], bdst[4];
#pragma unroll
    for (int i = 0; i < 2; i++) {
        int flat = tid + i * 512, row = flat >> 3, seg = flat & 7, ks = seg & 3;
        aoff[i] = ((seg < 4) ? 0 : aLo) + (bm * 128 + row) * K + ks * 8;
        adst[i] = ((seg < 4) ? S_AH : S_AL) + row * ASTRIDE + ks * 8;
    }
#pragma unroll
    for (int i = 0; i < 4; i++) {
        int flat = tid + i * 512, row = flat >> 3, seg = flat & 7, ks = seg & 3;
        boff[i] = ((seg < 4) ? 0 : wLo) + (bn * 256 + row) * K + ks * 8;
        bdst[i] = ((seg < 4) ? S_BH : S_BL) + row * ASTRIDE + ks * 8;
    }

#pragma unroll
    for (int c = 0; c < 2; c++) {
#pragma unroll
        for (int i = 0; i < 2; i++) cp16(sm + c * STAGE_ELEMS + adst[i], A + aoff[i] + c * 32);
#pragma unroll
        for (int i = 0; i < 4; i++) cp16(sm + c * STAGE_ELEMS + bdst[i], W + boff[i] + c * 32);
        cp_commit();
    }

    float acc[2][8][4];
#pragma unroll
    for (int a = 0; a < 2; a++)
#pragma unroll
        for (int b = 0; b < 8; b++)
#pragma unroll
            for (int c = 0; c < 4; c++) acc[a][b][c] = 0.f;

    const int aRow = wm * 32 + (lane & 8) + (lane & 7);
    const int aoffH_e = S_AH + aRow * ASTRIDE + ((lane & 16) >> 1);
    const int aoffL_e = S_AL + aRow * ASTRIDE + ((lane & 16) >> 1);
    const int bRow = wn * 64 + ((lane & 16) >> 1) + (lane & 7);
    const int boffH_e = S_BH + bRow * ASTRIDE + (lane & 8);
    const int boffL_e = S_BL + bRow * ASTRIDE + (lane & 8);

    const uint32_t smb = (uint32_t)__cvta_generic_to_shared(sm);

    int stage = 0;
    for (int ch = 0; ch < NCH; ch++) {
        cp_wait1();
        __syncthreads();

        if (ch + 2 < NCH) {
            int st2 = stage + 2; if (st2 >= 3) st2 -= 3;
#pragma unroll
            for (int i = 0; i < 2; i++)
                cp16(sm + st2 * STAGE_ELEMS + adst[i], A + aoff[i] + (ch + 2) * 32);
#pragma unroll
            for (int i = 0; i < 4; i++)
                cp16(sm + st2 * STAGE_ELEMS + bdst[i], W + boff[i] + (ch + 2) * 32);
        }
        cp_commit();

        const uint32_t sbase = smb + stage * (STAGE_ELEMS * 2);

#pragma unroll
        for (int kt = 0; kt < 2; kt++) {
            const uint32_t kbyte = kt * 32;

            unsigned ah[2][4];
#pragma unroll
            for (int mb = 0; mb < 2; mb++)
                ldsm4(ah[mb], sbase + (uint32_t)(aoffH_e + mb * 16 * ASTRIDE) * 2 + kbyte);

            unsigned bh[8][2];
#pragma unroll
            for (int p = 0; p < 4; p++) {
                unsigned r[4];
                ldsm4(r, sbase + (uint32_t)(boffH_e + p * 16 * ASTRIDE) * 2 + kbyte);
                bh[2*p][0] = r[0]; bh[2*p][1] = r[1];
                bh[2*p+1][0] = r[2]; bh[2*p+1][1] = r[3];
            }
#pragma unroll
            for (int mb = 0; mb < 2; mb++)
#pragma unroll
                for (int nb = 0; nb < 8; nb++) mma16(acc[mb][nb], ah[mb], bh[nb]);

            unsigned bl[8][2];
#pragma unroll
            for (int p = 0; p < 4; p++) {
                unsigned r[4];
                ldsm4(r, sbase + (uint32_t)(boffL_e + p * 16 * ASTRIDE) * 2 + kbyte);
                bl[2*p][0] = r[0]; bl[2*p][1] = r[1];
                bl[2*p+1][0] = r[2]; bl[2*p+1][1] = r[3];
            }
#pragma unroll
            for (int mb = 0; mb < 2; mb++)
#pragma unroll
                for (int nb = 0; nb < 8; nb++) mma16(acc[mb][nb], ah[mb], bl[nb]);

            unsigned al[2][4];
#pragma unroll
            for (int mb = 0; mb < 2; mb++)
                ldsm4(al[mb], sbase + (uint32_t)(aoffL_e + mb * 16 * ASTRIDE) * 2 + kbyte);
#pragma unroll
            for (int mb = 0; mb < 2; mb++)
#pragma unroll
                for (int nb = 0; nb < 8; nb++) mma16(acc[mb][nb], al[mb], bh[nb]);
        }
        stage++; if (stage >= 3) stage = 0;
    }

    const int g = lane >> 2, q2 = 2 * (lane & 3);
#pragma unroll
    for (int mb = 0; mb < 2; mb++) {
        int row0 = bm * 128 + wm * 32 + mb * 16 + g;
#pragma unroll
        for (int nb = 0; nb < 8; nb++) {
            int col = bn * 256 + wn * 64 + nb * 8 + q2;
            float b0 = __ldg(bias + col);
            float b1 = __ldg(bias + col + 1);
            int ra = row0, rb = row0 + 8;
            if (c_mode) {
                ra = (ra & 63) * 128 + (ra >> 6);
                rb = (rb & 63) * 128 + (rb >> 6);
            }
            *reinterpret_cast<float2*>(C + (size_t)ra * N + col) =
                make_float2(acc[mb][nb][0] + b0, acc[mb][nb][1] + b1);
            *reinterpret_cast<float2*>(C + (size_t)rb * N + col) =
                make_float2(acc[mb][nb][2] + b0, acc[mb][nb][3] + b1);
        }
    }
}

// ---------------------------------------------------------------------------
__global__ __launch_bounds__(256) void split_plain(
    const float* __restrict__ src, __nv_bfloat16* __restrict__ hi, __nv_bfloat16* __restrict__ lo)
{
    size_t i = (size_t)blockIdx.x * 256 + threadIdx.x;
    float4 v = *reinterpret_cast<const float4*>(src + i * 4);
    unsigned short h0,h1,h2,h3,l0,l1,l2,l3;
    split1(v.x,h0,l0); split1(v.y,h1,l1); split1(v.z,h2,l2); split1(v.w,h3,l3);
    *reinterpret_cast<uint2*>(hi + i * 4) = make_uint2(pack2(h0,h1), pack2(h2,h3));
    *reinterpret_cast<uint2*>(lo + i * 4) = make_uint2(pack2(l0,l1), pack2(l2,l3));
}

__global__ __launch_bounds__(256) void split_x(
    const float* __restrict__ hidden, __nv_bfloat16* __restrict__ hi, __nv_bfloat16* __restrict__ lo)
{
    size_t i = (size_t)blockIdx.x * 256 + threadIdx.x;
    int r = (int)(i >> 8);
    int c4 = ((int)i & 255) * 4;
    int s = r >> 9, b = (r >> 2) & 127, m = r & 3;
    const float4 v = *reinterpret_cast<const float4*>(
        hidden + (size_t)(s * 512 + m * 128 + b) * 1024 + c4);
    unsigned short h0,h1,h2,h3,l0,l1,l2,l3;
    split1(v.x,h0,l0); split1(v.y,h1,l1); split1(v.z,h2,l2); split1(v.w,h3,l3);
    *reinterpret_cast<uint2*>(hi + i * 4) = make_uint2(pack2(h0,h1), pack2(h2,h3));
    *reinterpret_cast<uint2*>(lo + i * 4) = make_uint2(pack2(l0,l1), pack2(l2,l3));
}

// ---------------------------------------------------------------------------
// Stage-1 attention, L=4, WITH fused mean over M (linearity: mean commutes
// with the projection). Writes ONE row per (sb, h): [8192, 1024] hi/lo.
__global__ __launch_bounds__(128) void attn_small(
    const float* __restrict__ qkv, __nv_bfloat16* __restrict__ ohi, __nv_bfloat16* __restrict__ olo)
{
    const int bid = blockIdx.x;
    const int sb = bid >> 3;
    const int h = bid & 7;
    const int t = threadIdx.x;

    const float* base = qkv + (size_t)sb * 4 * 3072 + h * 128 + t;
    float q[4], k[4], v[4];
#pragma unroll
    for (int m = 0; m < 4; m++) {
        q[m] = base[(size_t)m * 3072];
        k[m] = base[(size_t)m * 3072 + 1024];
        v[m] = base[(size_t)m * 3072 + 2048];
    }

    float p[16];
#pragma unroll
    for (int a = 0; a < 4; a++)
#pragma unroll
        for (int b = 0; b < 4; b++) p[a * 4 + b] = q[a] * k[b];

    __shared__ float red[4][16];
    __shared__ float ssc[16];
    const int lane = t & 31, w = t >> 5;
#pragma unroll
    for (int i = 0; i < 16; i++) {
        float x = p[i];
        x += __shfl_xor_sync(0xffffffffu, x, 16);
        x += __shfl_xor_sync(0xffffffffu, x, 8);
        x += __shfl_xor_sync(0xffffffffu, x, 4);
        x += __shfl_xor_sync(0xffffffffu, x, 2);
        x += __shfl_xor_sync(0xffffffffu, x, 1);
        if (lane == 0) red[w][i] = x;
    }
    __syncthreads();
    if (t < 16) ssc[t] = red[0][t] + red[1][t] + red[2][t] + red[3][t];
    __syncthreads();

    const float scale = 0.08838834764831845f;
    float osum = 0.f;
#pragma unroll
    for (int a = 0; a < 4; a++) {
        float s0 = ssc[a*4+0], s1 = ssc[a*4+1], s2 = ssc[a*4+2], s3 = ssc[a*4+3];
        float mx = fmaxf(fmaxf(s0, s1), fmaxf(s2, s3));
        float e0 = __expf((s0 - mx) * scale);
        float e1 = __expf((s1 - mx) * scale);
        float e2 = __expf((s2 - mx) * scale);
        float e3 = __expf((s3 - mx) * scale);
        float inv = 1.f / (e0 + e1 + e2 + e3);
        osum += (e0 * v[0] + e1 * v[1] + e2 * v[2] + e3 * v[3]) * inv;
    }
    osum *= 0.25f;

    size_t idx = (size_t)sb * 1024 + h * 128 + t;
    unsigned short hh, ll;
    split1(osum, hh, ll);
    ohi[idx] = __ushort_as_bfloat16(hh);
    olo[idx] = __ushort_as_bfloat16(ll);
}

// pos enc + layout change; y1 rows [s*128+b] -> seq row [b*64+s]; bf16 split out
__global__ __launch_bounds__(256) void reduce_pos(
    const float* __restrict__ y, const float* __restrict__ pos,
    __nv_bfloat16* __restrict__ shi, __nv_bfloat16* __restrict__ slo)
{
    int e = blockIdx.x * 256 + threadIdx.x;      // 8192*1024 elems
    int hcol = e & 1023;
    int bs = e >> 10;                            // b*64+s
    int b = bs >> 6, s = bs & 63;
    float v = y[(size_t)(s * 128 + b) * 1024 + hcol] + pos[s * 1024 + hcol];
    unsigned short hh, ll;
    split1(v, hh, ll);
    shi[e] = __ushort_as_bfloat16(hh);
    slo[e] = __ushort_as_bfloat16(ll);
}

// ---------------------------------------------------------------------------
#define AQ_STRIDE 68
#define AV_STRIDE 132
#define SC_STRIDE 65
#define ATTN2_SMEM ((128 * AQ_STRIDE * 2 + 64 * AV_STRIDE + 64 * SC_STRIDE) * 4)

__global__ __launch_bounds__(256) void attn_big(
    const float* __restrict__ qkv, __nv_bfloat16* __restrict__ ohi, __nv_bfloat16* __restrict__ olo)
{
    extern __shared__ float smf[];
    float* qs = smf;
    float* ks = qs + 128 * AQ_STRIDE;
    float* vs = ks + 128 * AQ_STRIDE;
    float* sc = vs + 64 * AV_STRIDE;

    const int bid = blockIdx.x;
    const int b = bid >> 3;
    const int h = bid & 7;
    const int t = threadIdx.x;

    const float* base = qkv + (size_t)b * 64 * 3072 + h * 128;

#pragma unroll
    for (int i = 0; i < 8; i++) {
        int flat = t + i * 256;
        int j = flat >> 5, d4 = flat & 31;
        const float* rp = base + (size_t)j * 3072 + d4 * 4;
        float4 qv = *reinterpret_cast<const float4*>(rp);
        float4 kv = *reinterpret_cast<const float4*>(rp + 1024);
        float4 vv = *reinterpret_cast<const float4*>(rp + 2048);
        int d0 = d4 * 4;
        qs[(d0+0)*AQ_STRIDE + j] = qv.x; qs[(d0+1)*AQ_STRIDE + j] = qv.y;
        qs[(d0+2)*AQ_STRIDE + j] = qv.z; qs[(d0+3)*AQ_STRIDE + j] = qv.w;
        ks[(d0+0)*AQ_STRIDE + j] = kv.x; ks[(d0+1)*AQ_STRIDE + j] = kv.y;
        ks[(d0+2)*AQ_STRIDE + j] = kv.z; ks[(d0+3)*AQ_STRIDE + j] = kv.w;
        *reinterpret_cast<float4*>(vs + j * AV_STRIDE + d0) = vv;
    }
    __syncthreads();

    {
        const int gi = t >> 4, gj = t & 15;
        float s4[4][4];
#pragma unroll
        for (int a = 0; a < 4; a++)
#pragma unroll
            for (int c = 0; c < 4; c++) s4[a][c] = 0.f;
#pragma unroll 4
        for (int d = 0; d < 128; d++) {
            float4 qv = *reinterpret_cast<const float4*>(qs + d * AQ_STRIDE + gi * 4);
            float4 kv = *reinterpret_cast<const float4*>(ks + d * AQ_STRIDE + gj * 4);
            float qa[4] = {qv.x, qv.y, qv.z, qv.w};
            float ka[4] = {kv.x, kv.y, kv.z, kv.w};
#pragma unroll
            for (int a = 0; a < 4; a++)
#pragma unroll
                for (int c = 0; c < 4; c++) s4[a][c] += qa[a] * ka[c];
        }
        int i0 = gi * 4, j0 = gj * 4;
#pragma unroll
        for (int a = 0; a < 4; a++) {
            float* r = sc + (i0 + a) * SC_STRIDE + j0;
            r[0]=s4[a][0]; r[1]=s4[a][1]; r[2]=s4[a][2]; r[3]=s4[a][3];
        }
    }
    __syncthreads();

    if (t < 64) {
        float* row = sc + t * SC_STRIDE;
        float mx = -1e30f;
#pragma unroll 8
        for (int j = 0; j < 64; j++) mx = fmaxf(mx, row[j]);
        const float scale = 0.08838834764831845f;
        float sum = 0.f;
#pragma unroll 8
        for (int j = 0; j < 64; j++) {
            float e = __expf((row[j] - mx) * scale);
            row[j] = e;
            sum += e;
        }
        float inv = 1.f / sum;
#pragma unroll 8
        for (int j = 0; j < 64; j++) row[j] *= inv;
    }
    __syncthreads();

    {
        const int gi = t >> 4, gd = t & 15;
        const int i0 = gi * 4;
        float o[4][8];
#pragma unroll
        for (int r = 0; r < 4; r++)
#pragma unroll
            for (int c = 0; c < 8; c++) o[r][c] = 0.f;
#pragma unroll 4
        for (int j = 0; j < 64; j++) {
            const float* vr = vs + j * AV_STRIDE + gd * 4;
            float p0 = sc[(i0+0)*SC_STRIDE + j];
            float p1 = sc[(i0+1)*SC_STRIDE + j];
            float p2 = sc[(i0+2)*SC_STRIDE + j];
            float p3 = sc[(i0+3)*SC_STRIDE + j];
#pragma unroll
            for (int c = 0; c < 4; c++) {
                float va = vr[c], vb = vr[64 + c];
                o[0][c] += p0*va; o[0][c+4] += p0*vb;
                o[1][c] += p1*va; o[1][c+4] += p1*vb;
                o[2][c] += p2*va; o[2][c+4] += p2*vb;
                o[3][c] += p3*va; o[3][c+4] += p3*vb;
            }
        }
#pragma unroll
        for (int r = 0; r < 4; r++) {
            size_t idx = (size_t)(b * 64 + i0 + r) * 1024 + h * 128 + gd * 4;
#pragma unroll
            for (int half = 0; half < 2; half++) {
                unsigned short h0,h1,h2,h3,l0,l1,l2,l3;
                split1(o[r][half*4+0], h0, l0);
                split1(o[r][half*4+1], h1, l1);
                split1(o[r][half*4+2], h2, l2);
                split1(o[r][half*4+3], h3, l3);
                size_t ix = idx + half * 64;
                *reinterpret_cast<uint2*>(ohi + ix) = make_uint2(pack2(h0,h1), pack2(h2,h3));
                *reinterpret_cast<uint2*>(olo + ix) = make_uint2(pack2(l0,l1), pack2(l2,l3));
            }
        }
    }
}

// ---------------------------------------------------------------------------
extern "C" void kernel_launch(void* const* d_in, const int* in_sizes, int n_in,
                              void* d_out, int out_size) {
    const float* hidden   = (const float*)d_in[0];
    const float* mf_in_w  = (const float*)d_in[1];
    const float* mf_in_b  = (const float*)d_in[2];
    const float* mf_out_w = (const float*)d_in[3];
    const float* mf_out_b = (const float*)d_in[4];
    const float* sf_in_w  = (const float*)d_in[5];
    const float* sf_in_b  = (const float*)d_in[6];
    const float* sf_out_w = (const float*)d_in[7];
    const float* sf_out_b = (const float*)d_in[8];
    const float* pos_enc  = (const float*)d_in[9];
    float* out = (float*)d_out;

    float *bufA;
    __nv_bfloat16 *bx, *bs, *bw;
    cudaGetSymbolAddress((void**)&bufA, g_bufA);
    cudaGetSymbolAddress((void**)&bx, g_x);
    cudaGetSymbolAddress((void**)&bs, g_s);
    cudaGetSymbolAddress((void**)&bw, g_w);

    cudaFuncSetAttribute(gemm_bf3, cudaFuncAttributeMaxDynamicSharedMemorySize, GEMM_SMEM);
    cudaFuncSetAttribute(attn_big, cudaFuncAttributeMaxDynamicSharedMemorySize, ATTN2_SMEM);

    // weight splits (hi at W_*, lo at +WLO)
    split_plain<<<3072, 256>>>(mf_in_w,  bw + W_MFIN,  bw + WLO + W_MFIN);
    split_plain<<<1024, 256>>>(mf_out_w, bw + W_MFOUT, bw + WLO + W_MFOUT);
    split_plain<<<3072, 256>>>(sf_in_w,  bw + W_SFIN,  bw + WLO + W_SFIN);
    split_plain<<<1024, 256>>>(sf_out_w, bw + W_SFOUT, bw + WLO + W_SFOUT);

    // x gather + split
    split_x<<<32768, 256>>>(hidden, bx, bx + XLO);

    // 1) qkv1 = x @ mf_in_w^T + b      [32768, 3072]
    gemm_bf3<<<dim3(12, 256), 512, GEMM_SMEM>>>(bx, XLO, bw + W_MFIN, WLO,
                                                mf_in_b, bufA, 3072, 1024, 0);
    // 2) MHA over M=4 + mean over M    -> [8192, 1024] hi/lo
    attn_small<<<65536, 128>>>(bufA, bx, bx + XLO);
    // 3) y1 = mean_attn @ mf_out_w^T + b   [8192, 1024]  (4x smaller than before)
    gemm_bf3<<<dim3(4, 64), 512, GEMM_SMEM>>>(bx, XLO, bw + W_MFOUT, WLO,
                                              mf_out_b, bufA, 1024, 1024, 0);
    // 4) + pos enc, reindex -> seq [b*64+s] (split)
    reduce_pos<<<32768, 256>>>(bufA, pos_enc, bs, bs + SLO);
    // 5) qkv2 = seq @ sf_in_w^T + b    [8192, 3072]
    gemm_bf3<<<dim3(12, 64), 512, GEMM_SMEM>>>(bs, SLO, bw + W_SFIN, WLO,
                                               sf_in_b, bufA, 3072, 1024, 0);
    // 6) MHA over S=64                 -> [8192, 1024] hi/lo
    attn_big<<<1024, 256, ATTN2_SMEM>>>(bufA, bx, bx + XLO);
    // 7) out = (attn2 @ sf_out_w^T + b), [b,s]->[s,b] transpose
    gemm_bf3<<<dim3(4, 64), 512, GEMM_SMEM>>>(bx, XLO, bw + W_SFOUT, WLO,
                                              sf_out_b, out, 1024, 1024, 1);
}